// round 6
// baseline (speedup 1.0000x reference)
#include <cuda_runtime.h>
#include <cuda_bf16.h>
#include <math.h>
#include <stdint.h>

#define BATCH 2
#define SEQ   2048
#define CH    1024
#define NHEAD 16
#define HD    64
#define MROWS (BATCH*SEQ)   // 4096

// ---------------------------------------------------------------------------
// scratch (device globals; allocation forbidden)
// ---------------------------------------------------------------------------
__device__ __nv_bfloat16 g_xhi[MROWS*CH];      // split of x; reused for att split
__device__ __nv_bfloat16 g_xlo[MROWS*CH];
__device__ __nv_bfloat16 g_qhi[MROWS*CH];
__device__ __nv_bfloat16 g_qlo[MROWS*CH];
__device__ __nv_bfloat16 g_khi[MROWS*CH];
__device__ __nv_bfloat16 g_klo[MROWS*CH];
__device__ __nv_bfloat16 g_vhi[MROWS*CH];
__device__ __nv_bfloat16 g_vlo[MROWS*CH];
__device__ __nv_bfloat16 g_wthi[4*CH*CH];
__device__ __nv_bfloat16 g_wtlo[4*CH*CH];

// ---------------------------------------------------------------------------
// helpers
// ---------------------------------------------------------------------------
__device__ __forceinline__ uint32_t smem_u32(const void* p) {
    uint32_t a;
    asm("{ .reg .u64 t; cvta.to.shared.u64 t, %1; cvt.u32.u64 %0, t; }"
        : "=r"(a) : "l"(p));
    return a;
}

__device__ __forceinline__ void mma16816(float c[4],
                                         uint32_t a0, uint32_t a1,
                                         uint32_t a2, uint32_t a3,
                                         uint32_t b0, uint32_t b1)
{
    asm volatile(
        "mma.sync.aligned.m16n8k16.row.col.f32.bf16.bf16.f32 "
        "{%0,%1,%2,%3}, {%4,%5,%6,%7}, {%8,%9}, {%0,%1,%2,%3};"
        : "+f"(c[0]), "+f"(c[1]), "+f"(c[2]), "+f"(c[3])
        : "r"(a0), "r"(a1), "r"(a2), "r"(a3), "r"(b0), "r"(b1));
}

#define LDSM_X4(r0,r1,r2,r3,a) \
    asm volatile("ldmatrix.sync.aligned.m8n8.x4.shared.b16 {%0,%1,%2,%3}, [%4];" \
        : "=r"(r0), "=r"(r1), "=r"(r2), "=r"(r3) : "r"(a))
#define LDSM_X4_T(r0,r1,r2,r3,a) \
    asm volatile("ldmatrix.sync.aligned.m8n8.x4.trans.shared.b16 {%0,%1,%2,%3}, [%4];" \
        : "=r"(r0), "=r"(r1), "=r"(r2), "=r"(r3) : "r"(a))

#define CP16(dst_u32, src) \
    asm volatile("cp.async.ca.shared.global [%0], [%1], 16;" \
        :: "r"(dst_u32), "l"(src) : "memory")
#define CP_COMMIT() asm volatile("cp.async.commit_group;" ::: "memory")
#define CP_WAIT0()  asm volatile("cp.async.wait_group 0;"  ::: "memory")

__device__ __forceinline__ void split2(float x, float y, uint32_t& hi, uint32_t& lo)
{
    __nv_bfloat16 hx = __float2bfloat16(x);
    __nv_bfloat16 hy = __float2bfloat16(y);
    __nv_bfloat16 lx = __float2bfloat16(x - __bfloat162float(hx));
    __nv_bfloat16 ly = __float2bfloat16(y - __bfloat162float(hy));
    __nv_bfloat162 hv(hx, hy), lv(lx, ly);
    hi = *(uint32_t*)&hv;
    lo = *(uint32_t*)&lv;
}

// ---------------------------------------------------------------------------
// fp32 -> bf16 hi/lo elementwise split
// ---------------------------------------------------------------------------
__global__ void split_kernel(const float* __restrict__ x,
                             __nv_bfloat16* __restrict__ hi,
                             __nv_bfloat16* __restrict__ lo, int n4)
{
    int i = blockIdx.x * blockDim.x + threadIdx.x;
    if (i >= n4) return;
    float4 v = ((const float4*)x)[i];
    float f[4] = {v.x, v.y, v.z, v.w};
    __nv_bfloat16 h[4], l[4];
#pragma unroll
    for (int u = 0; u < 4; u++) {
        h[u] = __float2bfloat16(f[u]);
        l[u] = __float2bfloat16(f[u] - __bfloat162float(h[u]));
    }
    ((uint2*)hi)[i] = *(uint2*)h;
    ((uint2*)lo)[i] = *(uint2*)l;
}

// ---------------------------------------------------------------------------
// W [K,N] fp32 -> W^T [N,K] bf16 hi/lo; grid.z selects which of 4 weights
// ---------------------------------------------------------------------------
struct TArgs { const float* W[4]; __nv_bfloat16* Th[4]; __nv_bfloat16* Tl[4]; };

__global__ void transpose_split_kernel(TArgs ta)
{
    __shared__ float t[32][33];
    const float* W = ta.W[blockIdx.z];
    __nv_bfloat16* Thi = ta.Th[blockIdx.z];
    __nv_bfloat16* Tlo = ta.Tl[blockIdx.z];
    const int kk = blockIdx.y * 32;
    const int nn = blockIdx.x * 32;
    const int tx = threadIdx.x, ty = threadIdx.y;
#pragma unroll
    for (int j = 0; j < 4; j++)
        t[ty + j * 8][tx] = W[(size_t)(kk + ty + j * 8) * CH + nn + tx];
    __syncthreads();
#pragma unroll
    for (int j = 0; j < 4; j++) {
        float v = t[tx][ty + j * 8];
        __nv_bfloat16 h = __float2bfloat16(v);
        __nv_bfloat16 l = __float2bfloat16(v - __bfloat162float(h));
        size_t o = (size_t)(nn + ty + j * 8) * CH + kk + tx;
        Thi[o] = h;
        Tlo[o] = l;
    }
}

// ---------------------------------------------------------------------------
// GEMM: out = (Ahi+Alo)[M,K] @ (Bhi+Blo)[N,K]^T + bias  (bf16x3 on HMMA)
// CTA 128x128, 8 warps (2x4), K-chunk 32, 2-stage cp.async pipeline.
// grid.z selects weight/out set. outf!=null -> fp32, else hi/lo split.
// ---------------------------------------------------------------------------
#define P2   40                       // smem row pitch (32 data + 8 pad)
#define ARRB (128*P2*2)               // bytes per array per stage
#define STGB (4*ARRB)                 // bytes per stage

struct GemmArgs {
    const __nv_bfloat16* Bh[3];
    const __nv_bfloat16* Bl[3];
    const float* bias[3];
    float* outf[3];
    __nv_bfloat16* oh[3];
    __nv_bfloat16* ol[3];
};

__global__ void __launch_bounds__(256, 2)
gemm_mma_bf16x3(const __nv_bfloat16* __restrict__ Ahi,
                const __nv_bfloat16* __restrict__ Alo,
                GemmArgs ga, int K, int N)
{
    extern __shared__ __nv_bfloat16 sm[];
    const uint32_t ub = smem_u32(sm);
    const int z = blockIdx.z;
    const __nv_bfloat16* Bhi = ga.Bh[z];
    const __nv_bfloat16* Blo = ga.Bl[z];

    const int tid  = threadIdx.x;
    const int warp = tid >> 5;
    const int lane = tid & 31;
    const int grp  = lane >> 2;
    const int tig  = lane & 3;
    const int wm   = warp >> 2;
    const int wn   = warp & 3;
    const int m0 = blockIdx.y * 128;
    const int n0 = blockIdx.x * 128;

    float c[4][4][4];
#pragma unroll
    for (int mt = 0; mt < 4; mt++)
#pragma unroll
        for (int nt = 0; nt < 4; nt++)
#pragma unroll
            for (int f = 0; f < 4; f++) c[mt][nt][f] = 0.f;

    // loader indices: 2 units/thread/array; unit = row*4 + cg (16B groups)
    const int u0 = tid * 2;
    const int lrow0 = u0 >> 2, lcg0 = u0 & 3;
    const int lrow1 = (u0 + 1) >> 2, lcg1 = (u0 + 1) & 3;

    auto load_chunk = [&](int k0, int s) {
        uint32_t sb = ub + s * STGB;
        {
            size_t ga_ = (size_t)(m0 + lrow0) * K + k0 + lcg0 * 8;
            size_t gb_ = (size_t)(n0 + lrow0) * K + k0 + lcg0 * 8;
            uint32_t so = (uint32_t)(lrow0 * P2 + lcg0 * 8) * 2;
            CP16(sb + 0 * ARRB + so, Ahi + ga_);
            CP16(sb + 1 * ARRB + so, Alo + ga_);
            CP16(sb + 2 * ARRB + so, Bhi + gb_);
            CP16(sb + 3 * ARRB + so, Blo + gb_);
        }
        {
            size_t ga_ = (size_t)(m0 + lrow1) * K + k0 + lcg1 * 8;
            size_t gb_ = (size_t)(n0 + lrow1) * K + k0 + lcg1 * 8;
            uint32_t so = (uint32_t)(lrow1 * P2 + lcg1 * 8) * 2;
            CP16(sb + 0 * ARRB + so, Ahi + ga_);
            CP16(sb + 1 * ARRB + so, Alo + ga_);
            CP16(sb + 2 * ARRB + so, Bhi + gb_);
            CP16(sb + 3 * ARRB + so, Blo + gb_);
        }
    };

    const int nc = K / 32;
    load_chunk(0, 0);
    CP_COMMIT();

    for (int ch = 0; ch < nc; ch++) {
        CP_WAIT0();
        __syncthreads();
        if (ch + 1 < nc) { load_chunk((ch + 1) * 32, (ch + 1) & 1); CP_COMMIT(); }

        const __nv_bfloat16* st = sm + (size_t)(ch & 1) * (STGB / 2);
        const __nv_bfloat16* sAh = st;
        const __nv_bfloat16* sAl = st + 128 * P2;
        const __nv_bfloat16* sBh = st + 2 * 128 * P2;
        const __nv_bfloat16* sBl = st + 3 * 128 * P2;

#pragma unroll
        for (int ks = 0; ks < 2; ks++) {
            const int kof = ks * 16 + 2 * tig;
            uint32_t bh[4][2], bl[4][2];
#pragma unroll
            for (int nt = 0; nt < 4; nt++) {
                int nrow = wn * 32 + nt * 8 + grp;
                bh[nt][0] = *(const uint32_t*)&sBh[nrow * P2 + kof];
                bh[nt][1] = *(const uint32_t*)&sBh[nrow * P2 + kof + 8];
                bl[nt][0] = *(const uint32_t*)&sBl[nrow * P2 + kof];
                bl[nt][1] = *(const uint32_t*)&sBl[nrow * P2 + kof + 8];
            }
#pragma unroll
            for (int mt = 0; mt < 4; mt++) {
                int mrow = wm * 64 + mt * 16 + grp;
                uint32_t ah0 = *(const uint32_t*)&sAh[mrow * P2 + kof];
                uint32_t ah1 = *(const uint32_t*)&sAh[(mrow + 8) * P2 + kof];
                uint32_t ah2 = *(const uint32_t*)&sAh[mrow * P2 + kof + 8];
                uint32_t ah3 = *(const uint32_t*)&sAh[(mrow + 8) * P2 + kof + 8];
                uint32_t al0 = *(const uint32_t*)&sAl[mrow * P2 + kof];
                uint32_t al1 = *(const uint32_t*)&sAl[(mrow + 8) * P2 + kof];
                uint32_t al2 = *(const uint32_t*)&sAl[mrow * P2 + kof + 8];
                uint32_t al3 = *(const uint32_t*)&sAl[(mrow + 8) * P2 + kof + 8];
#pragma unroll
                for (int nt = 0; nt < 4; nt++) {
                    mma16816(c[mt][nt], ah0, ah1, ah2, ah3, bh[nt][0], bh[nt][1]);
                    mma16816(c[mt][nt], ah0, ah1, ah2, ah3, bl[nt][0], bl[nt][1]);
                    mma16816(c[mt][nt], al0, al1, al2, al3, bh[nt][0], bh[nt][1]);
                }
            }
        }
        __syncthreads();
    }

    const float* bias = ga.bias[z];
    float* outf = ga.outf[z];
    __nv_bfloat16* oh = ga.oh[z];
    __nv_bfloat16* ol = ga.ol[z];
#pragma unroll
    for (int mt = 0; mt < 4; mt++) {
        int r0 = m0 + wm * 64 + mt * 16 + grp;
#pragma unroll
        for (int nt = 0; nt < 4; nt++) {
            int col = n0 + wn * 32 + nt * 8 + 2 * tig;
            float2 bv = *(const float2*)(bias + col);
            float v00 = c[mt][nt][0] + bv.x, v01 = c[mt][nt][1] + bv.y;
            float v10 = c[mt][nt][2] + bv.x, v11 = c[mt][nt][3] + bv.y;
            if (outf) {
                *(float2*)(outf + (size_t)r0 * N + col) = make_float2(v00, v01);
                *(float2*)(outf + (size_t)(r0 + 8) * N + col) = make_float2(v10, v11);
            } else {
                uint32_t h0, l0, h1, l1;
                split2(v00, v01, h0, l0);
                split2(v10, v11, h1, l1);
                *(uint32_t*)(oh + (size_t)r0 * N + col) = h0;
                *(uint32_t*)(ol + (size_t)r0 * N + col) = l0;
                *(uint32_t*)(oh + (size_t)(r0 + 8) * N + col) = h1;
                *(uint32_t*)(ol + (size_t)(r0 + 8) * N + col) = l1;
            }
        }
    }
}

// ---------------------------------------------------------------------------
// HMMA flash attention (swapped roles), ldmatrix fragment loads.
// Br=Bc=64, 4 warps, warp = 16 i-rows. V stored row-major; PV uses
// ldmatrix.x4.trans. bf16x3 split on S and PV; P stays in registers.
// ---------------------------------------------------------------------------
#define AP 72

__global__ void __launch_bounds__(128, 3)
attn_mma(const __nv_bfloat16* __restrict__ qhi, const __nv_bfloat16* __restrict__ qlo,
         const __nv_bfloat16* __restrict__ khi, const __nv_bfloat16* __restrict__ klo,
         const __nv_bfloat16* __restrict__ vhi, const __nv_bfloat16* __restrict__ vlo,
         __nv_bfloat16* __restrict__ ohi, __nv_bfloat16* __restrict__ olo)
{
    extern __shared__ __nv_bfloat16 sa[];
    __nv_bfloat16* sQh = sa;                    // [64][AP] rows i (k-buffer)
    __nv_bfloat16* sQl = sa + 64 * AP;
    __nv_bfloat16* sKh = sa + 2 * 64 * AP;      // [64][AP] rows j (q-buffer)
    __nv_bfloat16* sKl = sa + 3 * 64 * AP;
    __nv_bfloat16* sVh = sa + 4 * 64 * AP;      // [64][AP] row-major [j][d]
    __nv_bfloat16* sVl = sa + 5 * 64 * AP;

    const uint32_t ub  = smem_u32(sa);
    const uint32_t uQh = ub;
    const uint32_t uQl = ub + 1 * 64 * AP * 2;
    const uint32_t uKh = ub + 2 * 64 * AP * 2;
    const uint32_t uKl = ub + 3 * 64 * AP * 2;
    const uint32_t uVh = ub + 4 * 64 * AP * 2;
    const uint32_t uVl = ub + 5 * 64 * AP * 2;

    const int tid  = threadIdx.x;
    const int warp = tid >> 5;
    const int lane = tid & 31;
    const int g    = lane >> 2;
    const int tig  = lane & 3;

    // heavy tiles first (better causal load balance)
    const int i0 = (gridDim.x - 1 - blockIdx.x) * 64;
    const int bh = blockIdx.y;
    const int b  = bh >> 4;
    const int h  = bh & 15;
    const size_t base = (size_t)b * SEQ * CH + (size_t)h * HD;

    // ldmatrix lane-address offsets (bytes)
    const uint32_t qoff = ((warp * 16 + (lane & 15)) * AP + ((lane >> 4) << 3)) * 2;
    const uint32_t koff = (((((lane >> 4) << 3) + (lane & 7)) * AP) + (((lane >> 3) & 1) << 3)) * 2;
    const uint32_t voff = (((((lane >> 3) & 1) << 3) + (lane & 7)) * AP + ((lane >> 4) << 3)) * 2;

    // load Q tile (= k rows i0..i0+63)
    {
        int r = tid >> 3, cg = tid & 7;
#pragma unroll
        for (int i = 0; i < 4; i++) {
            int rr = r + i * 16;
            size_t go = base + (size_t)(i0 + rr) * CH + cg * 8;
            *(uint4*)&sQh[rr * AP + cg * 8] = *(const uint4*)(khi + go);
            *(uint4*)&sQl[rr * AP + cg * 8] = *(const uint4*)(klo + go);
        }
    }

    float acc[8][4];
#pragma unroll
    for (int nd = 0; nd < 8; nd++)
#pragma unroll
        for (int f = 0; f < 4; f++) acc[nd][f] = 0.f;
    float m0r = -INFINITY, m1r = -INFINITY, l0r = 0.f, l1r = 0.f;

    const float scl = 0.125f * 1.44269504f;
    const int ig0 = i0 + warp * 16 + g;
    const int ig1 = ig0 + 8;

    for (int j0 = 0; j0 <= i0; j0 += 64) {
        __syncthreads();
        // K tile (= q rows) and V tile (row-major), uint4 stores
        {
            int r = tid >> 3, cg = tid & 7;
#pragma unroll
            for (int i = 0; i < 4; i++) {
                int rr = r + i * 16;
                size_t go = base + (size_t)(j0 + rr) * CH + cg * 8;
                int so = rr * AP + cg * 8;
                *(uint4*)&sKh[so] = *(const uint4*)(qhi + go);
                *(uint4*)&sKl[so] = *(const uint4*)(qlo + go);
                *(uint4*)&sVh[so] = *(const uint4*)(vhi + go);
                *(uint4*)&sVl[so] = *(const uint4*)(vlo + go);
            }
        }
        __syncthreads();

        // ----- S = Q . K^T  (bf16x3) -----
        float sf[8][4];
#pragma unroll
        for (int nt = 0; nt < 8; nt++)
#pragma unroll
            for (int f = 0; f < 4; f++) sf[nt][f] = 0.f;

#pragma unroll
        for (int kd = 0; kd < 4; kd++) {
            uint32_t ah0, ah1, ah2, ah3, al0, al1, al2, al3;
            LDSM_X4(ah0, ah1, ah2, ah3, uQh + qoff + kd * 32);
            LDSM_X4(al0, al1, al2, al3, uQl + qoff + kd * 32);
#pragma unroll
            for (int ntp = 0; ntp < 4; ntp++) {
                const int nt = ntp * 2;
                const uint32_t off = koff + nt * (8 * AP * 2) + kd * 32;
                uint32_t kh0, kh1, kh2, kh3, kl0, kl1, kl2, kl3;
                LDSM_X4(kh0, kh1, kh2, kh3, uKh + off);
                LDSM_X4(kl0, kl1, kl2, kl3, uKl + off);
                mma16816(sf[nt],     ah0, ah1, ah2, ah3, kh0, kh1);
                mma16816(sf[nt],     ah0, ah1, ah2, ah3, kl0, kl1);
                mma16816(sf[nt],     al0, al1, al2, al3, kh0, kh1);
                mma16816(sf[nt + 1], ah0, ah1, ah2, ah3, kh2, kh3);
                mma16816(sf[nt + 1], ah0, ah1, ah2, ah3, kl2, kl3);
                mma16816(sf[nt + 1], al0, al1, al2, al3, kh2, kh3);
            }
        }

        // scale (log2 domain) + causal mask on diagonal tile
        if (j0 == i0) {
#pragma unroll
            for (int nt = 0; nt < 8; nt++)
#pragma unroll
                for (int cc = 0; cc < 2; cc++) {
                    int jg = j0 + nt * 8 + 2 * tig + cc;
                    sf[nt][cc]     = (jg <= ig0) ? sf[nt][cc] * scl     : -INFINITY;
                    sf[nt][2 + cc] = (jg <= ig1) ? sf[nt][2 + cc] * scl : -INFINITY;
                }
        } else {
#pragma unroll
            for (int nt = 0; nt < 8; nt++)
#pragma unroll
                for (int f = 0; f < 4; f++) sf[nt][f] *= scl;
        }

        // ----- online softmax (rows g, g+8) -----
        float mx0 = -INFINITY, mx1 = -INFINITY;
#pragma unroll
        for (int nt = 0; nt < 8; nt++) {
            mx0 = fmaxf(mx0, fmaxf(sf[nt][0], sf[nt][1]));
            mx1 = fmaxf(mx1, fmaxf(sf[nt][2], sf[nt][3]));
        }
        mx0 = fmaxf(mx0, __shfl_xor_sync(0xffffffffu, mx0, 1));
        mx0 = fmaxf(mx0, __shfl_xor_sync(0xffffffffu, mx0, 2));
        mx1 = fmaxf(mx1, __shfl_xor_sync(0xffffffffu, mx1, 1));
        mx1 = fmaxf(mx1, __shfl_xor_sync(0xffffffffu, mx1, 2));

        float mn0 = fmaxf(m0r, mx0), mn1 = fmaxf(m1r, mx1);
        float a0f = exp2f(m0r - mn0), a1f = exp2f(m1r - mn1);
        m0r = mn0; m1r = mn1;

        float ps0 = 0.f, ps1 = 0.f;
#pragma unroll
        for (int nt = 0; nt < 8; nt++) {
            sf[nt][0] = exp2f(sf[nt][0] - mn0);
            sf[nt][1] = exp2f(sf[nt][1] - mn0);
            sf[nt][2] = exp2f(sf[nt][2] - mn1);
            sf[nt][3] = exp2f(sf[nt][3] - mn1);
            ps0 += sf[nt][0] + sf[nt][1];
            ps1 += sf[nt][2] + sf[nt][3];
        }
        ps0 += __shfl_xor_sync(0xffffffffu, ps0, 1);
        ps0 += __shfl_xor_sync(0xffffffffu, ps0, 2);
        ps1 += __shfl_xor_sync(0xffffffffu, ps1, 1);
        ps1 += __shfl_xor_sync(0xffffffffu, ps1, 2);
        l0r = l0r * a0f + ps0;
        l1r = l1r * a1f + ps1;

#pragma unroll
        for (int nd = 0; nd < 8; nd++) {
            acc[nd][0] *= a0f; acc[nd][1] *= a0f;
            acc[nd][2] *= a1f; acc[nd][3] *= a1f;
        }

        // ----- acc += P @ V  (ldmatrix.trans on row-major V, bf16x3) -----
#pragma unroll
        for (int ks = 0; ks < 4; ks++) {
            uint32_t ph0, pl0, ph1, pl1, ph2, pl2, ph3, pl3;
            split2(sf[2 * ks][0],     sf[2 * ks][1],     ph0, pl0);
            split2(sf[2 * ks][2],     sf[2 * ks][3],     ph1, pl1);
            split2(sf[2 * ks + 1][0], sf[2 * ks + 1][1], ph2, pl2);
            split2(sf[2 * ks + 1][2], sf[2 * ks + 1][3], ph3, pl3);
#pragma unroll
            for (int ndp = 0; ndp < 4; ndp++) {
                const int nd = ndp * 2;
                const uint32_t off = voff + ks * (16 * AP * 2) + nd * 16;
                uint32_t vh0, vh1, vh2, vh3, vl0, vl1, vl2, vl3;
                LDSM_X4_T(vh0, vh1, vh2, vh3, uVh + off);
                LDSM_X4_T(vl0, vl1, vl2, vl3, uVl + off);
                mma16816(acc[nd],     ph0, ph1, ph2, ph3, vh0, vh1);
                mma16816(acc[nd],     ph0, ph1, ph2, ph3, vl0, vl1);
                mma16816(acc[nd],     pl0, pl1, pl2, pl3, vh0, vh1);
                mma16816(acc[nd + 1], ph0, ph1, ph2, ph3, vh2, vh3);
                mma16816(acc[nd + 1], ph0, ph1, ph2, ph3, vl2, vl3);
                mma16816(acc[nd + 1], pl0, pl1, pl2, pl3, vh2, vh3);
            }
        }
    }

    // ----- epilogue -----
    const float inv0 = 1.f / l0r, inv1 = 1.f / l1r;
    const size_t r0o = base + (size_t)ig0 * CH;
    const size_t r1o = base + (size_t)ig1 * CH;
#pragma unroll
    for (int nd = 0; nd < 8; nd++) {
        int col = nd * 8 + 2 * tig;
        uint32_t h0, l0, h1, l1;
        split2(acc[nd][0] * inv0, acc[nd][1] * inv0, h0, l0);
        split2(acc[nd][2] * inv1, acc[nd][3] * inv1, h1, l1);
        *(uint32_t*)(ohi + r0o + col) = h0;
        *(uint32_t*)(olo + r0o + col) = l0;
        *(uint32_t*)(ohi + r1o + col) = h1;
        *(uint32_t*)(olo + r1o + col) = l1;
    }
}

// ---------------------------------------------------------------------------
extern "C" void kernel_launch(void* const* d_in, const int* in_sizes, int n_in,
                              void* d_out, int out_size)
{
    const float* x  = (const float*)d_in[0];
    const float* Wq = (const float*)d_in[1];
    const float* bq = (const float*)d_in[2];
    const float* Wk = (const float*)d_in[3];
    const float* bk = (const float*)d_in[4];
    const float* Wv = (const float*)d_in[5];
    const float* bv = (const float*)d_in[6];
    const float* Wp = (const float*)d_in[7];
    const float* bp = (const float*)d_in[8];
    float* out = (float*)d_out;

    __nv_bfloat16 *xhi, *xlo, *qhi, *qlo, *khi, *klo, *vhi, *vlo, *wthi, *wtlo;
    cudaGetSymbolAddress((void**)&xhi,  g_xhi);
    cudaGetSymbolAddress((void**)&xlo,  g_xlo);
    cudaGetSymbolAddress((void**)&qhi,  g_qhi);
    cudaGetSymbolAddress((void**)&qlo,  g_qlo);
    cudaGetSymbolAddress((void**)&khi,  g_khi);
    cudaGetSymbolAddress((void**)&klo,  g_klo);
    cudaGetSymbolAddress((void**)&vhi,  g_vhi);
    cudaGetSymbolAddress((void**)&vlo,  g_vlo);
    cudaGetSymbolAddress((void**)&wthi, g_wthi);
    cudaGetSymbolAddress((void**)&wtlo, g_wtlo);

    const int gemm_smem = 2 * STGB;                                  // 81920
    const int attn_smem = 6 * 64 * AP * (int)sizeof(__nv_bfloat16);  // 55296
    cudaFuncSetAttribute(gemm_mma_bf16x3, cudaFuncAttributeMaxDynamicSharedMemorySize, gemm_smem);
    cudaFuncSetAttribute(attn_mma, cudaFuncAttributeMaxDynamicSharedMemorySize, attn_smem);

    // weight transposes (one launch, z = 4)
    TArgs ta;
    ta.W[0] = Wq; ta.W[1] = Wk; ta.W[2] = Wv; ta.W[3] = Wp;
    for (int i = 0; i < 4; i++) { ta.Th[i] = wthi + (size_t)i * CH * CH;
                                  ta.Tl[i] = wtlo + (size_t)i * CH * CH; }
    transpose_split_kernel<<<dim3(CH / 32, CH / 32, 4), dim3(32, 8)>>>(ta);

    split_kernel<<<MROWS * CH / (256 * 4), 256>>>(x, xhi, xlo, MROWS * CH / 4);

    // q,k,v projections (one launch, z = 3)
    GemmArgs gq = {};
    gq.Bh[0] = wthi; gq.Bh[1] = wthi + CH * CH; gq.Bh[2] = wthi + 2 * CH * CH;
    gq.Bl[0] = wtlo; gq.Bl[1] = wtlo + CH * CH; gq.Bl[2] = wtlo + 2 * CH * CH;
    gq.bias[0] = bq; gq.bias[1] = bk; gq.bias[2] = bv;
    gq.outf[0] = gq.outf[1] = gq.outf[2] = nullptr;
    gq.oh[0] = qhi; gq.oh[1] = khi; gq.oh[2] = vhi;
    gq.ol[0] = qlo; gq.ol[1] = klo; gq.ol[2] = vlo;
    gemm_mma_bf16x3<<<dim3(CH / 128, MROWS / 128, 3), 256, gemm_smem>>>(xhi, xlo, gq, CH, CH);

    // attention -> hi/lo split into xhi/xlo
    attn_mma<<<dim3(SEQ / 64, BATCH * NHEAD), 128, attn_smem>>>(qhi, qlo, khi, klo, vhi, vlo,
                                                                xhi, xlo);

    // output projection
    GemmArgs gp = {};
    gp.Bh[0] = wthi + 3 * CH * CH;
    gp.Bl[0] = wtlo + 3 * CH * CH;
    gp.bias[0] = bp;
    gp.outf[0] = out;
    gemm_mma_bf16x3<<<dim3(CH / 128, MROWS / 128, 1), 256, gemm_smem>>>(xhi, xlo, gp, CH, CH);
}

// round 7
// speedup vs baseline: 1.2516x; 1.2516x over previous
#include <cuda_runtime.h>
#include <cuda_bf16.h>
#include <math.h>
#include <stdint.h>

#define BATCH 2
#define SEQ   2048
#define CH    1024
#define NHEAD 16
#define HD    64
#define MROWS (BATCH*SEQ)   // 4096

// ---------------------------------------------------------------------------
// scratch (device globals; allocation forbidden)
// ---------------------------------------------------------------------------
__device__ __nv_bfloat16 g_xhi[MROWS*CH];      // split of x; reused for att split
__device__ __nv_bfloat16 g_xlo[MROWS*CH];
__device__ __nv_bfloat16 g_qhi[MROWS*CH];
__device__ __nv_bfloat16 g_qlo[MROWS*CH];
__device__ __nv_bfloat16 g_khi[MROWS*CH];
__device__ __nv_bfloat16 g_klo[MROWS*CH];
__device__ __nv_bfloat16 g_vhi[MROWS*CH];
__device__ __nv_bfloat16 g_vlo[MROWS*CH];
__device__ __nv_bfloat16 g_wthi[4*CH*CH];
__device__ __nv_bfloat16 g_wtlo[4*CH*CH];

// ---------------------------------------------------------------------------
// helpers
// ---------------------------------------------------------------------------
__device__ __forceinline__ uint32_t smem_u32(const void* p) {
    uint32_t a;
    asm("{ .reg .u64 t; cvta.to.shared.u64 t, %1; cvt.u32.u64 %0, t; }"
        : "=r"(a) : "l"(p));
    return a;
}

__device__ __forceinline__ void mma16816(float c[4],
                                         uint32_t a0, uint32_t a1,
                                         uint32_t a2, uint32_t a3,
                                         uint32_t b0, uint32_t b1)
{
    asm volatile(
        "mma.sync.aligned.m16n8k16.row.col.f32.bf16.bf16.f32 "
        "{%0,%1,%2,%3}, {%4,%5,%6,%7}, {%8,%9}, {%0,%1,%2,%3};"
        : "+f"(c[0]), "+f"(c[1]), "+f"(c[2]), "+f"(c[3])
        : "r"(a0), "r"(a1), "r"(a2), "r"(a3), "r"(b0), "r"(b1));
}

#define LDSM_X4(r0,r1,r2,r3,a) \
    asm volatile("ldmatrix.sync.aligned.m8n8.x4.shared.b16 {%0,%1,%2,%3}, [%4];" \
        : "=r"(r0), "=r"(r1), "=r"(r2), "=r"(r3) : "r"(a))
#define LDSM_X4_T(r0,r1,r2,r3,a) \
    asm volatile("ldmatrix.sync.aligned.m8n8.x4.trans.shared.b16 {%0,%1,%2,%3}, [%4];" \
        : "=r"(r0), "=r"(r1), "=r"(r2), "=r"(r3) : "r"(a))

__device__ __forceinline__ void split2(float x, float y, uint32_t& hi, uint32_t& lo)
{
    __nv_bfloat16 hx = __float2bfloat16(x);
    __nv_bfloat16 hy = __float2bfloat16(y);
    __nv_bfloat16 lx = __float2bfloat16(x - __bfloat162float(hx));
    __nv_bfloat16 ly = __float2bfloat16(y - __bfloat162float(hy));
    __nv_bfloat162 hv(hx, hy), lv(lx, ly);
    hi = *(uint32_t*)&hv;
    lo = *(uint32_t*)&lv;
}

// ---------------------------------------------------------------------------
// fp32 -> bf16 hi/lo elementwise split
// ---------------------------------------------------------------------------
__global__ void split_kernel(const float* __restrict__ x,
                             __nv_bfloat16* __restrict__ hi,
                             __nv_bfloat16* __restrict__ lo, int n4)
{
    int i = blockIdx.x * blockDim.x + threadIdx.x;
    if (i >= n4) return;
    float4 v = ((const float4*)x)[i];
    float f[4] = {v.x, v.y, v.z, v.w};
    __nv_bfloat16 h[4], l[4];
#pragma unroll
    for (int u = 0; u < 4; u++) {
        h[u] = __float2bfloat16(f[u]);
        l[u] = __float2bfloat16(f[u] - __bfloat162float(h[u]));
    }
    ((uint2*)hi)[i] = *(uint2*)h;
    ((uint2*)lo)[i] = *(uint2*)l;
}

// ---------------------------------------------------------------------------
// W [K,N] fp32 -> W^T [N,K] bf16 hi/lo; grid.z selects which of 4 weights
// ---------------------------------------------------------------------------
struct TArgs { const float* W[4]; __nv_bfloat16* Th[4]; __nv_bfloat16* Tl[4]; };

__global__ void transpose_split_kernel(TArgs ta)
{
    __shared__ float t[32][33];
    const float* W = ta.W[blockIdx.z];
    __nv_bfloat16* Thi = ta.Th[blockIdx.z];
    __nv_bfloat16* Tlo = ta.Tl[blockIdx.z];
    const int kk = blockIdx.y * 32;
    const int nn = blockIdx.x * 32;
    const int tx = threadIdx.x, ty = threadIdx.y;
#pragma unroll
    for (int j = 0; j < 4; j++)
        t[ty + j * 8][tx] = W[(size_t)(kk + ty + j * 8) * CH + nn + tx];
    __syncthreads();
#pragma unroll
    for (int j = 0; j < 4; j++) {
        float v = t[tx][ty + j * 8];
        __nv_bfloat16 h = __float2bfloat16(v);
        __nv_bfloat16 l = __float2bfloat16(v - __bfloat162float(h));
        size_t o = (size_t)(nn + ty + j * 8) * CH + kk + tx;
        Thi[o] = h;
        Tlo[o] = l;
    }
}

// ---------------------------------------------------------------------------
// GEMM: out = (Ahi+Alo)[M,K] @ (Bhi+Blo)[N,K]^T + bias  (bf16x3 on HMMA)
// CTA 128x128, 8 warps (2x4), warp tile 64x32, K-chunk 64, synchronous loads
// (round-5 mainloop — measured ~65us/GEMM). grid.z selects weight/out set.
// ---------------------------------------------------------------------------
#define PITCH 72

struct GemmArgs {
    const __nv_bfloat16* Bh[3];
    const __nv_bfloat16* Bl[3];
    const float* bias[3];
    float* outf[3];
    __nv_bfloat16* oh[3];
    __nv_bfloat16* ol[3];
};

__global__ void __launch_bounds__(256, 2)
gemm_mma_bf16x3(const __nv_bfloat16* __restrict__ Ahi,
                const __nv_bfloat16* __restrict__ Alo,
                GemmArgs ga, int K, int N)
{
    extern __shared__ __nv_bfloat16 sm[];
    __nv_bfloat16* sAh = sm;
    __nv_bfloat16* sAl = sm + 128 * PITCH;
    __nv_bfloat16* sBh = sm + 2 * 128 * PITCH;
    __nv_bfloat16* sBl = sm + 3 * 128 * PITCH;

    const int z = blockIdx.z;
    const __nv_bfloat16* Bhi = ga.Bh[z];
    const __nv_bfloat16* Blo = ga.Bl[z];

    const int tid  = threadIdx.x;
    const int warp = tid >> 5;
    const int lane = tid & 31;
    const int grp  = lane >> 2;
    const int tig  = lane & 3;
    const int wm   = warp >> 2;
    const int wn   = warp & 3;
    const int m0 = blockIdx.y * 128;
    const int n0 = blockIdx.x * 128;

    float c[4][4][4];
#pragma unroll
    for (int mt = 0; mt < 4; mt++)
#pragma unroll
        for (int nt = 0; nt < 4; nt++)
#pragma unroll
            for (int f = 0; f < 4; f++) c[mt][nt][f] = 0.f;

    const int row = tid >> 3;
    const int cg  = tid & 7;

    for (int k0 = 0; k0 < K; k0 += 64) {
        __syncthreads();
#pragma unroll
        for (int i = 0; i < 4; i++) {
            int r = row + i * 32;
            size_t ga_ = (size_t)(m0 + r) * K + k0 + cg * 8;
            size_t gb_ = (size_t)(n0 + r) * K + k0 + cg * 8;
            int so = r * PITCH + cg * 8;
            *(uint4*)&sAh[so] = *(const uint4*)(Ahi + ga_);
            *(uint4*)&sAl[so] = *(const uint4*)(Alo + ga_);
            *(uint4*)&sBh[so] = *(const uint4*)(Bhi + gb_);
            *(uint4*)&sBl[so] = *(const uint4*)(Blo + gb_);
        }
        __syncthreads();

#pragma unroll
        for (int ks = 0; ks < 4; ks++) {
            const int kof = ks * 16 + 2 * tig;
            uint32_t bh[4][2], bl[4][2];
#pragma unroll
            for (int nt = 0; nt < 4; nt++) {
                int nrow = wn * 32 + nt * 8 + grp;
                bh[nt][0] = *(const uint32_t*)&sBh[nrow * PITCH + kof];
                bh[nt][1] = *(const uint32_t*)&sBh[nrow * PITCH + kof + 8];
                bl[nt][0] = *(const uint32_t*)&sBl[nrow * PITCH + kof];
                bl[nt][1] = *(const uint32_t*)&sBl[nrow * PITCH + kof + 8];
            }
#pragma unroll
            for (int mt = 0; mt < 4; mt++) {
                int mrow = wm * 64 + mt * 16 + grp;
                uint32_t ah0 = *(const uint32_t*)&sAh[mrow * PITCH + kof];
                uint32_t ah1 = *(const uint32_t*)&sAh[(mrow + 8) * PITCH + kof];
                uint32_t ah2 = *(const uint32_t*)&sAh[mrow * PITCH + kof + 8];
                uint32_t ah3 = *(const uint32_t*)&sAh[(mrow + 8) * PITCH + kof + 8];
                uint32_t al0 = *(const uint32_t*)&sAl[mrow * PITCH + kof];
                uint32_t al1 = *(const uint32_t*)&sAl[(mrow + 8) * PITCH + kof];
                uint32_t al2 = *(const uint32_t*)&sAl[mrow * PITCH + kof + 8];
                uint32_t al3 = *(const uint32_t*)&sAl[(mrow + 8) * PITCH + kof + 8];
#pragma unroll
                for (int nt = 0; nt < 4; nt++) {
                    mma16816(c[mt][nt], ah0, ah1, ah2, ah3, bh[nt][0], bh[nt][1]);
                    mma16816(c[mt][nt], ah0, ah1, ah2, ah3, bl[nt][0], bl[nt][1]);
                    mma16816(c[mt][nt], al0, al1, al2, al3, bh[nt][0], bh[nt][1]);
                }
            }
        }
    }

    const float* bias = ga.bias[z];
    float* outf = ga.outf[z];
    __nv_bfloat16* oh = ga.oh[z];
    __nv_bfloat16* ol = ga.ol[z];
#pragma unroll
    for (int mt = 0; mt < 4; mt++) {
        int r0 = m0 + wm * 64 + mt * 16 + grp;
#pragma unroll
        for (int nt = 0; nt < 4; nt++) {
            int col = n0 + wn * 32 + nt * 8 + 2 * tig;
            float2 bv = *(const float2*)(bias + col);
            float v00 = c[mt][nt][0] + bv.x, v01 = c[mt][nt][1] + bv.y;
            float v10 = c[mt][nt][2] + bv.x, v11 = c[mt][nt][3] + bv.y;
            if (outf) {
                *(float2*)(outf + (size_t)r0 * N + col) = make_float2(v00, v01);
                *(float2*)(outf + (size_t)(r0 + 8) * N + col) = make_float2(v10, v11);
            } else {
                uint32_t h0, l0, h1, l1;
                split2(v00, v01, h0, l0);
                split2(v10, v11, h1, l1);
                *(uint32_t*)(oh + (size_t)r0 * N + col) = h0;
                *(uint32_t*)(ol + (size_t)r0 * N + col) = l0;
                *(uint32_t*)(oh + (size_t)(r0 + 8) * N + col) = h1;
                *(uint32_t*)(ol + (size_t)(r0 + 8) * N + col) = l1;
            }
        }
    }
}

// ---------------------------------------------------------------------------
// HMMA flash attention (swapped roles), ldmatrix fragment loads.
// Br=Bc=64, 4 warps, warp = 16 i-rows. V stored row-major; PV uses
// ldmatrix.x4.trans. bf16x3 split on S and PV; P stays in registers.
// (unchanged from round 6 — measured 192.5us)
// ---------------------------------------------------------------------------
#define AP 72

__global__ void __launch_bounds__(128, 3)
attn_mma(const __nv_bfloat16* __restrict__ qhi, const __nv_bfloat16* __restrict__ qlo,
         const __nv_bfloat16* __restrict__ khi, const __nv_bfloat16* __restrict__ klo,
         const __nv_bfloat16* __restrict__ vhi, const __nv_bfloat16* __restrict__ vlo,
         __nv_bfloat16* __restrict__ ohi, __nv_bfloat16* __restrict__ olo)
{
    extern __shared__ __nv_bfloat16 sa[];
    __nv_bfloat16* sQh = sa;
    __nv_bfloat16* sQl = sa + 64 * AP;
    __nv_bfloat16* sKh = sa + 2 * 64 * AP;
    __nv_bfloat16* sKl = sa + 3 * 64 * AP;
    __nv_bfloat16* sVh = sa + 4 * 64 * AP;
    __nv_bfloat16* sVl = sa + 5 * 64 * AP;

    const uint32_t ub  = smem_u32(sa);
    const uint32_t uQh = ub;
    const uint32_t uQl = ub + 1 * 64 * AP * 2;
    const uint32_t uKh = ub + 2 * 64 * AP * 2;
    const uint32_t uKl = ub + 3 * 64 * AP * 2;
    const uint32_t uVh = ub + 4 * 64 * AP * 2;
    const uint32_t uVl = ub + 5 * 64 * AP * 2;

    const int tid  = threadIdx.x;
    const int warp = tid >> 5;
    const int lane = tid & 31;
    const int g    = lane >> 2;
    const int tig  = lane & 3;

    const int i0 = (gridDim.x - 1 - blockIdx.x) * 64;
    const int bh = blockIdx.y;
    const int b  = bh >> 4;
    const int h  = bh & 15;
    const size_t base = (size_t)b * SEQ * CH + (size_t)h * HD;

    const uint32_t qoff = ((warp * 16 + (lane & 15)) * AP + ((lane >> 4) << 3)) * 2;
    const uint32_t koff = (((((lane >> 4) << 3) + (lane & 7)) * AP) + (((lane >> 3) & 1) << 3)) * 2;
    const uint32_t voff = (((((lane >> 3) & 1) << 3) + (lane & 7)) * AP + ((lane >> 4) << 3)) * 2;

    {
        int r = tid >> 3, cg = tid & 7;
#pragma unroll
        for (int i = 0; i < 4; i++) {
            int rr = r + i * 16;
            size_t go = base + (size_t)(i0 + rr) * CH + cg * 8;
            *(uint4*)&sQh[rr * AP + cg * 8] = *(const uint4*)(khi + go);
            *(uint4*)&sQl[rr * AP + cg * 8] = *(const uint4*)(klo + go);
        }
    }

    float acc[8][4];
#pragma unroll
    for (int nd = 0; nd < 8; nd++)
#pragma unroll
        for (int f = 0; f < 4; f++) acc[nd][f] = 0.f;
    float m0r = -INFINITY, m1r = -INFINITY, l0r = 0.f, l1r = 0.f;

    const float scl = 0.125f * 1.44269504f;
    const int ig0 = i0 + warp * 16 + g;
    const int ig1 = ig0 + 8;

    for (int j0 = 0; j0 <= i0; j0 += 64) {
        __syncthreads();
        {
            int r = tid >> 3, cg = tid & 7;
#pragma unroll
            for (int i = 0; i < 4; i++) {
                int rr = r + i * 16;
                size_t go = base + (size_t)(j0 + rr) * CH + cg * 8;
                int so = rr * AP + cg * 8;
                *(uint4*)&sKh[so] = *(const uint4*)(qhi + go);
                *(uint4*)&sKl[so] = *(const uint4*)(qlo + go);
                *(uint4*)&sVh[so] = *(const uint4*)(vhi + go);
                *(uint4*)&sVl[so] = *(const uint4*)(vlo + go);
            }
        }
        __syncthreads();

        float sf[8][4];
#pragma unroll
        for (int nt = 0; nt < 8; nt++)
#pragma unroll
            for (int f = 0; f < 4; f++) sf[nt][f] = 0.f;

#pragma unroll
        for (int kd = 0; kd < 4; kd++) {
            uint32_t ah0, ah1, ah2, ah3, al0, al1, al2, al3;
            LDSM_X4(ah0, ah1, ah2, ah3, uQh + qoff + kd * 32);
            LDSM_X4(al0, al1, al2, al3, uQl + qoff + kd * 32);
#pragma unroll
            for (int ntp = 0; ntp < 4; ntp++) {
                const int nt = ntp * 2;
                const uint32_t off = koff + nt * (8 * AP * 2) + kd * 32;
                uint32_t kh0, kh1, kh2, kh3, kl0, kl1, kl2, kl3;
                LDSM_X4(kh0, kh1, kh2, kh3, uKh + off);
                LDSM_X4(kl0, kl1, kl2, kl3, uKl + off);
                mma16816(sf[nt],     ah0, ah1, ah2, ah3, kh0, kh1);
                mma16816(sf[nt],     ah0, ah1, ah2, ah3, kl0, kl1);
                mma16816(sf[nt],     al0, al1, al2, al3, kh0, kh1);
                mma16816(sf[nt + 1], ah0, ah1, ah2, ah3, kh2, kh3);
                mma16816(sf[nt + 1], ah0, ah1, ah2, ah3, kl2, kl3);
                mma16816(sf[nt + 1], al0, al1, al2, al3, kh2, kh3);
            }
        }

        if (j0 == i0) {
#pragma unroll
            for (int nt = 0; nt < 8; nt++)
#pragma unroll
                for (int cc = 0; cc < 2; cc++) {
                    int jg = j0 + nt * 8 + 2 * tig + cc;
                    sf[nt][cc]     = (jg <= ig0) ? sf[nt][cc] * scl     : -INFINITY;
                    sf[nt][2 + cc] = (jg <= ig1) ? sf[nt][2 + cc] * scl : -INFINITY;
                }
        } else {
#pragma unroll
            for (int nt = 0; nt < 8; nt++)
#pragma unroll
                for (int f = 0; f < 4; f++) sf[nt][f] *= scl;
        }

        float mx0 = -INFINITY, mx1 = -INFINITY;
#pragma unroll
        for (int nt = 0; nt < 8; nt++) {
            mx0 = fmaxf(mx0, fmaxf(sf[nt][0], sf[nt][1]));
            mx1 = fmaxf(mx1, fmaxf(sf[nt][2], sf[nt][3]));
        }
        mx0 = fmaxf(mx0, __shfl_xor_sync(0xffffffffu, mx0, 1));
        mx0 = fmaxf(mx0, __shfl_xor_sync(0xffffffffu, mx0, 2));
        mx1 = fmaxf(mx1, __shfl_xor_sync(0xffffffffu, mx1, 1));
        mx1 = fmaxf(mx1, __shfl_xor_sync(0xffffffffu, mx1, 2));

        float mn0 = fmaxf(m0r, mx0), mn1 = fmaxf(m1r, mx1);
        float a0f = exp2f(m0r - mn0), a1f = exp2f(m1r - mn1);
        m0r = mn0; m1r = mn1;

        float ps0 = 0.f, ps1 = 0.f;
#pragma unroll
        for (int nt = 0; nt < 8; nt++) {
            sf[nt][0] = exp2f(sf[nt][0] - mn0);
            sf[nt][1] = exp2f(sf[nt][1] - mn0);
            sf[nt][2] = exp2f(sf[nt][2] - mn1);
            sf[nt][3] = exp2f(sf[nt][3] - mn1);
            ps0 += sf[nt][0] + sf[nt][1];
            ps1 += sf[nt][2] + sf[nt][3];
        }
        ps0 += __shfl_xor_sync(0xffffffffu, ps0, 1);
        ps0 += __shfl_xor_sync(0xffffffffu, ps0, 2);
        ps1 += __shfl_xor_sync(0xffffffffu, ps1, 1);
        ps1 += __shfl_xor_sync(0xffffffffu, ps1, 2);
        l0r = l0r * a0f + ps0;
        l1r = l1r * a1f + ps1;

#pragma unroll
        for (int nd = 0; nd < 8; nd++) {
            acc[nd][0] *= a0f; acc[nd][1] *= a0f;
            acc[nd][2] *= a1f; acc[nd][3] *= a1f;
        }

#pragma unroll
        for (int ks = 0; ks < 4; ks++) {
            uint32_t ph0, pl0, ph1, pl1, ph2, pl2, ph3, pl3;
            split2(sf[2 * ks][0],     sf[2 * ks][1],     ph0, pl0);
            split2(sf[2 * ks][2],     sf[2 * ks][3],     ph1, pl1);
            split2(sf[2 * ks + 1][0], sf[2 * ks + 1][1], ph2, pl2);
            split2(sf[2 * ks + 1][2], sf[2 * ks + 1][3], ph3, pl3);
#pragma unroll
            for (int ndp = 0; ndp < 4; ndp++) {
                const int nd = ndp * 2;
                const uint32_t off = voff + ks * (16 * AP * 2) + nd * 16;
                uint32_t vh0, vh1, vh2, vh3, vl0, vl1, vl2, vl3;
                LDSM_X4_T(vh0, vh1, vh2, vh3, uVh + off);
                LDSM_X4_T(vl0, vl1, vl2, vl3, uVl + off);
                mma16816(acc[nd],     ph0, ph1, ph2, ph3, vh0, vh1);
                mma16816(acc[nd],     ph0, ph1, ph2, ph3, vl0, vl1);
                mma16816(acc[nd],     pl0, pl1, pl2, pl3, vh0, vh1);
                mma16816(acc[nd + 1], ph0, ph1, ph2, ph3, vh2, vh3);
                mma16816(acc[nd + 1], ph0, ph1, ph2, ph3, vl2, vl3);
                mma16816(acc[nd + 1], pl0, pl1, pl2, pl3, vh2, vh3);
            }
        }
    }

    const float inv0 = 1.f / l0r, inv1 = 1.f / l1r;
    const size_t r0o = base + (size_t)ig0 * CH;
    const size_t r1o = base + (size_t)ig1 * CH;
#pragma unroll
    for (int nd = 0; nd < 8; nd++) {
        int col = nd * 8 + 2 * tig;
        uint32_t h0, l0, h1, l1;
        split2(acc[nd][0] * inv0, acc[nd][1] * inv0, h0, l0);
        split2(acc[nd][2] * inv1, acc[nd][3] * inv1, h1, l1);
        *(uint32_t*)(ohi + r0o + col) = h0;
        *(uint32_t*)(olo + r0o + col) = l0;
        *(uint32_t*)(ohi + r1o + col) = h1;
        *(uint32_t*)(olo + r1o + col) = l1;
    }
}

// ---------------------------------------------------------------------------
extern "C" void kernel_launch(void* const* d_in, const int* in_sizes, int n_in,
                              void* d_out, int out_size)
{
    const float* x  = (const float*)d_in[0];
    const float* Wq = (const float*)d_in[1];
    const float* bq = (const float*)d_in[2];
    const float* Wk = (const float*)d_in[3];
    const float* bk = (const float*)d_in[4];
    const float* Wv = (const float*)d_in[5];
    const float* bv = (const float*)d_in[6];
    const float* Wp = (const float*)d_in[7];
    const float* bp = (const float*)d_in[8];
    float* out = (float*)d_out;

    __nv_bfloat16 *xhi, *xlo, *qhi, *qlo, *khi, *klo, *vhi, *vlo, *wthi, *wtlo;
    cudaGetSymbolAddress((void**)&xhi,  g_xhi);
    cudaGetSymbolAddress((void**)&xlo,  g_xlo);
    cudaGetSymbolAddress((void**)&qhi,  g_qhi);
    cudaGetSymbolAddress((void**)&qlo,  g_qlo);
    cudaGetSymbolAddress((void**)&khi,  g_khi);
    cudaGetSymbolAddress((void**)&klo,  g_klo);
    cudaGetSymbolAddress((void**)&vhi,  g_vhi);
    cudaGetSymbolAddress((void**)&vlo,  g_vlo);
    cudaGetSymbolAddress((void**)&wthi, g_wthi);
    cudaGetSymbolAddress((void**)&wtlo, g_wtlo);

    const int gemm_smem = 4 * 128 * PITCH * (int)sizeof(__nv_bfloat16);  // 73728
    const int attn_smem = 6 * 64 * AP * (int)sizeof(__nv_bfloat16);      // 55296
    cudaFuncSetAttribute(gemm_mma_bf16x3, cudaFuncAttributeMaxDynamicSharedMemorySize, gemm_smem);
    cudaFuncSetAttribute(attn_mma, cudaFuncAttributeMaxDynamicSharedMemorySize, attn_smem);

    // weight transposes (one launch, z = 4)
    TArgs ta;
    ta.W[0] = Wq; ta.W[1] = Wk; ta.W[2] = Wv; ta.W[3] = Wp;
    for (int i = 0; i < 4; i++) { ta.Th[i] = wthi + (size_t)i * CH * CH;
                                  ta.Tl[i] = wtlo + (size_t)i * CH * CH; }
    transpose_split_kernel<<<dim3(CH / 32, CH / 32, 4), dim3(32, 8)>>>(ta);

    split_kernel<<<MROWS * CH / (256 * 4), 256>>>(x, xhi, xlo, MROWS * CH / 4);

    // q,k,v projections (one launch, z = 3)
    GemmArgs gq = {};
    gq.Bh[0] = wthi; gq.Bh[1] = wthi + CH * CH; gq.Bh[2] = wthi + 2 * CH * CH;
    gq.Bl[0] = wtlo; gq.Bl[1] = wtlo + CH * CH; gq.Bl[2] = wtlo + 2 * CH * CH;
    gq.bias[0] = bq; gq.bias[1] = bk; gq.bias[2] = bv;
    gq.outf[0] = gq.outf[1] = gq.outf[2] = nullptr;
    gq.oh[0] = qhi; gq.oh[1] = khi; gq.oh[2] = vhi;
    gq.ol[0] = qlo; gq.ol[1] = klo; gq.ol[2] = vlo;
    gemm_mma_bf16x3<<<dim3(CH / 128, MROWS / 128, 3), 256, gemm_smem>>>(xhi, xlo, gq, CH, CH);

    // attention -> hi/lo split into xhi/xlo
    attn_mma<<<dim3(SEQ / 64, BATCH * NHEAD), 128, attn_smem>>>(qhi, qlo, khi, klo, vhi, vlo,
                                                                xhi, xlo);

    // output projection
    GemmArgs gp = {};
    gp.Bh[0] = wthi + 3 * CH * CH;
    gp.Bl[0] = wtlo + 3 * CH * CH;
    gp.bias[0] = bp;
    gp.outf[0] = out;
    gemm_mma_bf16x3<<<dim3(CH / 128, MROWS / 128, 1), 256, gemm_smem>>>(xhi, xlo, gp, CH, CH);
}